// round 7
// baseline (speedup 1.0000x reference)
#include <cuda_runtime.h>
#include <cuda_bf16.h>

namespace {

constexpr int B  = 256;
constexpr int L  = 128;
constexpr int H  = 512;
constexpr int H4 = 2048;

typedef unsigned long long ull;

// ---------------- device state (allocation-free scratch) ----------------
__device__ float g_h[2][B * H];                          // hidden, double buffered by parity
__device__ float g_c[B * H];                             // cell
__device__ float g_enc_out[(size_t)B * L * H];           // fp32 [b*L+l][h] (encw1 A input)
__device__ __nv_bfloat16 g_enc_outh[(size_t)B * L * H];  // bf16 [b][l][h] (attn context)
__device__ __nv_bfloat16 g_enc_w1h[(size_t)B * L * H];   // bf16 [b*L+l][h] (attn scores)
__device__ float g_ctx[B * H];                           // attention context [b][h]
__device__ float g_q[B * H];                             // q = h @ w2^T (reduced)
__device__ float g_dec_in[2][B];                         // decoder scalar input
__device__ float g_ewh4[H4 * H];                         // enc_Wh, gate-interleaved [n'=4h+g][k]
__device__ float g_eb4[H4];                              // enc bias, interleaved
__device__ float g_ewi4[H4];                             // enc Wi (scalar input), interleaved
__device__ float g_dw4[H4 * 1024];                       // dec [Wi(ctx)|Wh], interleaved, stride 1024
__device__ float g_db4[H4];
__device__ float g_dwi4[H4];                             // dec Wi last column, interleaved
__device__ float g_zpart[(size_t)8 * B * H4];            // split-K partials (LSTM), [kz][b][n']
__device__ float g_qpartb[(size_t)8 * B * H];            // split-K partials (qproj)
__device__ int   g_cnt[64];                              // per-tile arrival counters

// ---------------- math helpers ----------------
__device__ __forceinline__ float sigmoid_acc(float x) {
    return 1.0f / (1.0f + __expf(-x));
}
__device__ __forceinline__ float tanh_acc(float x) {
    float e = __expf(-2.0f * fabsf(x));
    float r = (1.0f - e) / (1.0f + e);
    return copysignf(r, x);
}
__device__ __forceinline__ float tanh_fast(float x) {
    float y;
    asm("tanh.approx.f32 %0, %1;" : "=f"(y) : "f"(x));
    return y;
}
__device__ __forceinline__ void ffma2(ull& d, ull a, ull b) {
    asm("fma.rn.f32x2 %0, %1, %2, %0;" : "+l"(d) : "l"(a), "l"(b));
}
__device__ __forceinline__ ull pk2(float x, float y) {
    ull r;
    asm("mov.b64 %0, {%1, %2};" : "=l"(r) : "f"(x), "f"(y));
    return r;
}
__device__ __forceinline__ float2 f2bits(ull v) {
    return *reinterpret_cast<float2*>(&v);
}

// ---------------- init ----------------
__global__ void k_init() {
    int i = blockIdx.x * blockDim.x + threadIdx.x;
    int stride = gridDim.x * blockDim.x;
    for (int j = i; j < B * H; j += stride) {
        g_h[0][j] = 0.0f;
        g_c[j]    = 0.0f;
    }
    if (i < B) g_dec_in[0][i] = 0.0f;
    if (i < 64) g_cnt[i] = 0;
}

// ---------------- one-time repacks: gate-interleave (n' = 4h + g) ----------------
__global__ void k_repack_enc(const float* __restrict__ ewh,
                             const float* __restrict__ eb,
                             const float* __restrict__ ewi) {
    int i = blockIdx.x * blockDim.x + threadIdx.x;
    int stride = gridDim.x * blockDim.x;
    for (int j = i; j < H4 * H; j += stride) {
        int np = j >> 9;
        int k  = j & (H - 1);
        int hh = np >> 2, g = np & 3;
        g_ewh4[j] = ewh[(g * H + hh) * H + k];
    }
    if (i < H4) {
        int hh = i >> 2, g = i & 3;
        g_eb4[i]  = eb[g * H + hh];
        g_ewi4[i] = ewi[g * H + hh];
    }
}

__global__ void k_repack_dec(const float* __restrict__ dwi,
                             const float* __restrict__ dwh,
                             const float* __restrict__ db) {
    int i = blockIdx.x * blockDim.x + threadIdx.x;
    int stride = gridDim.x * blockDim.x;
    for (int j = i; j < H4 * 1024; j += stride) {
        int np = j >> 10;
        int k  = j & 1023;
        int hh = np >> 2, g = np & 3;
        int row = g * H + hh;
        g_dw4[j] = (k < H) ? dwi[row * (H + 1) + k] : dwh[row * H + (k - H)];
    }
    if (i < H4) {
        int hh = i >> 2, g = i & 3;
        g_db4[i]  = db[g * H + hh];
        g_dwi4[i] = dwi[(g * H + hh) * (H + 1) + H];
    }
}

// ======================================================================================
// 128x128 GEMM core, 256 threads, 8x8 micro via FFMA2. A k-rows from gmem (stride 512),
// W rows [n][KTOT]. Split-K with last-CTA inline fixup epilogue.
// EPI: 0 = enc LSTM gates, 1 = dec LSTM gates, 2 = store q, 3 = bf16 store (encw1, KS=1)
// ======================================================================================
template <int KTOT, int KS, int NOUT, int EPI>
__global__ void __launch_bounds__(256) k_gemm(
    const float* __restrict__ W,
    const float* __restrict__ A0,
    const float* __restrict__ A1,      // dec: h (ctx in A0)
    float* __restrict__ part,          // [KS][256][NOUT]
    const float* __restrict__ bias4,
    const float* __restrict__ wiv4,
    const int*   __restrict__ xs,
    const int*   __restrict__ argsort,
    int t)
{
    constexpr int KC  = KTOT / KS;
    constexpr int NKT = KC / 16;

    __shared__ float As[2][16][132];
    __shared__ float Bs[2][16][132];
    __shared__ int s_flag;

    const int tid = threadIdx.x;
    const int tx  = tid & 15;
    const int ty  = tid >> 4;
    const int n0  = blockIdx.x * 128;
    const int m0  = blockIdx.y * 128;
    const int kc  = blockIdx.z * KC;
    const int p   = t & 1;

    const float* Ab;
    if (EPI == 1) {
        Ab = (kc < 512) ? (A0 + kc) : (A1 + (kc - 512));
    } else {
        Ab = A0 + kc;
    }

    const int lrow = tid >> 1;           // 0..127
    const int lkq  = (tid & 1) * 8;      // 0 or 8

    ull acc[4][8] = {};

    float a_r[8], w_r[8];
    auto gload = [&](int k0) {
        const float* ap = Ab + (size_t)(m0 + lrow) * 512 + k0 + lkq;
        const float* wp = W + (size_t)(n0 + lrow) * KTOT + kc + k0 + lkq;
        *(float4*)&a_r[0] = *(const float4*)ap;
        *(float4*)&a_r[4] = *(const float4*)(ap + 4);
        *(float4*)&w_r[0] = *(const float4*)wp;
        *(float4*)&w_r[4] = *(const float4*)(wp + 4);
    };
    auto sstore = [&](int buf) {
#pragma unroll
        for (int i = 0; i < 8; i++) {
            As[buf][lkq + i][lrow] = a_r[i];
            Bs[buf][lkq + i][lrow] = w_r[i];
        }
    };

    gload(0);
    sstore(0);
    __syncthreads();

    for (int it = 0; it < NKT; it++) {
        const bool more = (it + 1 < NKT);
        if (more) gload((it + 1) * 16);

        const int cb = it & 1;
#pragma unroll
        for (int k = 0; k < 16; k++) {
            ulonglong2 aLo = *(const ulonglong2*)&As[cb][k][ty * 4];
            ulonglong2 aHi = *(const ulonglong2*)&As[cb][k][64 + ty * 4];
            float4 bLo = *(const float4*)&Bs[cb][k][tx * 4];
            float4 bHi = *(const float4*)&Bs[cb][k][64 + tx * 4];
            ull am[4] = {aLo.x, aLo.y, aHi.x, aHi.y};
            ull bd[8] = {pk2(bLo.x, bLo.x), pk2(bLo.y, bLo.y),
                         pk2(bLo.z, bLo.z), pk2(bLo.w, bLo.w),
                         pk2(bHi.x, bHi.x), pk2(bHi.y, bHi.y),
                         pk2(bHi.z, bHi.z), pk2(bHi.w, bHi.w)};
#pragma unroll
            for (int mp = 0; mp < 4; mp++) {
#pragma unroll
                for (int n = 0; n < 8; n++) ffma2(acc[mp][n], am[mp], bd[n]);
            }
        }
        if (more) sstore(cb ^ 1);
        __syncthreads();
    }

    // ---------------- epilogue ----------------
    if (EPI == 3) {
        // direct bf16 store (KS == 1): thread owns m rows {ty*4+j, 64+ty*4+j}, n cols {tx*4.., 64+tx*4..}
#pragma unroll
        for (int j = 0; j < 8; j++) {
            const int ml = (j < 4) ? (ty * 4 + j) : (64 + ty * 4 + (j - 4));
            const int mp = (j < 4) ? (j >> 1) : (2 + ((j - 4) >> 1));
            const int lane = j & 1;
            float v[8];
#pragma unroll
            for (int n = 0; n < 8; n++) {
                float2 f = f2bits(acc[mp][n]);
                v[n] = lane ? f.y : f.x;
            }
            const size_t mrow = (size_t)(m0 + ml) * 512;
            __nv_bfloat162 p0 = __floats2bfloat162_rn(v[0], v[1]);
            __nv_bfloat162 p1 = __floats2bfloat162_rn(v[2], v[3]);
            *(uint2*)&g_enc_w1h[mrow + n0 + tx * 4] = make_uint2(*(unsigned*)&p0, *(unsigned*)&p1);
            __nv_bfloat162 p2 = __floats2bfloat162_rn(v[4], v[5]);
            __nv_bfloat162 p3 = __floats2bfloat162_rn(v[6], v[7]);
            *(uint2*)&g_enc_w1h[mrow + n0 + 64 + tx * 4] = make_uint2(*(unsigned*)&p2, *(unsigned*)&p3);
        }
        return;
    }

    // store partials
#pragma unroll
    for (int j = 0; j < 8; j++) {
        const int ml = (j < 4) ? (ty * 4 + j) : (64 + ty * 4 + (j - 4));
        const int mp = (j < 4) ? (j >> 1) : (2 + ((j - 4) >> 1));
        const int lane = j & 1;
        float v[8];
#pragma unroll
        for (int n = 0; n < 8; n++) {
            float2 f = f2bits(acc[mp][n]);
            v[n] = lane ? f.y : f.x;
        }
        float* dst = part + ((size_t)blockIdx.z * 256 + m0 + ml) * NOUT + n0;
        *(float4*)&dst[tx * 4]      = make_float4(v[0], v[1], v[2], v[3]);
        *(float4*)&dst[64 + tx * 4] = make_float4(v[4], v[5], v[6], v[7]);
    }

    __syncthreads();
    __threadfence();
    if (tid == 0) {
        int c = atomicAdd(&g_cnt[blockIdx.y * gridDim.x + blockIdx.x], 1);
        s_flag = (c == KS - 1) ? 1 : 0;
    }
    __syncthreads();
    if (!s_flag) return;
    if (tid == 0) g_cnt[blockIdx.y * gridDim.x + blockIdx.x] = 0;
    __threadfence();

    if (EPI == 2) {
        // q fixup: reduce partials, store fp32 q
#pragma unroll 1
        for (int r = 0; r < 16; r++) {
            const int id  = (r << 8) + tid;
            const int row = id >> 5;           // 0..127
            const int col = id & 31;           // 0..31 -> 4 floats
            const int b   = m0 + row;
            const int n   = n0 + (col << 2);
            float4 z = make_float4(0.f, 0.f, 0.f, 0.f);
#pragma unroll
            for (int kz = 0; kz < KS; kz++) {
                float4 vv = *(const float4*)&part[((size_t)kz * 256 + b) * NOUT + n];
                z.x += vv.x; z.y += vv.y; z.z += vv.z; z.w += vv.w;
            }
            *(float4*)&g_q[b * H + n] = z;
        }
        return;
    }

    // LSTM gate fixup: each (b, h) pair = 4 interleaved gates
#pragma unroll 1
    for (int r = 0; r < 16; r++) {
        const int id = (r << 8) + tid;
        const int bl = id >> 5;                // 0..127
        const int hl = id & 31;                // 0..31
        const int b  = m0 + bl;
        const int np = n0 + (hl << 2);
        float4 z = make_float4(0.f, 0.f, 0.f, 0.f);
#pragma unroll
        for (int kz = 0; kz < KS; kz++) {
            float4 vv = *(const float4*)&part[((size_t)kz * 256 + b) * NOUT + np];
            z.x += vv.x; z.y += vv.y; z.z += vv.z; z.w += vv.w;
        }
        const float4 bb = *(const float4*)&bias4[np];
        const float4 ww = *(const float4*)&wiv4[np];
        const float xb = (EPI == 0) ? (float)xs[b * L + t] : g_dec_in[p][b];
        const float zi = z.x + bb.x + xb * ww.x;
        const float zf = z.y + bb.y + xb * ww.y;
        const float zg = z.z + bb.z + xb * ww.z;
        const float zo = z.w + bb.w + xb * ww.w;
        const int h  = (n0 >> 2) + hl;
        const int ci = b * H + h;
        const float c  = sigmoid_acc(zf) * g_c[ci] + sigmoid_acc(zi) * tanh_acc(zg);
        const float hn = sigmoid_acc(zo) * tanh_acc(c);
        g_c[ci] = c;
        g_h[p ^ 1][ci] = hn;
        if (EPI == 0) {
            const size_t eo = ((size_t)b * L + t) * H + h;
            g_enc_out[eo]  = hn;
            g_enc_outh[eo] = __float2bfloat16_rn(hn);
        } else {
            if (blockIdx.x == 0 && hl == 0) {
                g_dec_in[p ^ 1][b] = (float)xs[b * L + argsort[b * L + t]];
            }
        }
    }
}

// ---------------- attention: scores + softmax/log_softmax + context ----------------
__global__ void __launch_bounds__(256) k_attn(const float* __restrict__ vt,
                                              float* __restrict__ out, int t) {
    __shared__ float q_s[H];
    __shared__ float vt_s[H];
    __shared__ float sc[L];
    __shared__ float aj[L];

    const int b = blockIdx.x;
    const int tid = threadIdx.x;
    const int lane = tid & 31;
    const int w = tid >> 5;

    for (int i = tid; i < H; i += 256) {
        q_s[i]  = g_q[b * H + i];
        vt_s[i] = vt[i];
    }
    __syncthreads();

#pragma unroll 1
    for (int li = 0; li < 16; li++) {
        const int l = w * 16 + li;
        const uint4* e8 = (const uint4*)(g_enc_w1h + (size_t)(b * L + l) * H);
        float s = 0.f;
#pragma unroll
        for (int j = 0; j < 2; j++) {
            const int base = (lane + j * 32) * 8;
            uint4 u = e8[lane + j * 32];
            float4 q0 = *(const float4*)&q_s[base];
            float4 q1 = *(const float4*)&q_s[base + 4];
            float4 v0 = *(const float4*)&vt_s[base];
            float4 v1 = *(const float4*)&vt_s[base + 4];
            float2 e0 = __bfloat1622float2(*(__nv_bfloat162*)&u.x);
            float2 e1 = __bfloat1622float2(*(__nv_bfloat162*)&u.y);
            float2 e2 = __bfloat1622float2(*(__nv_bfloat162*)&u.z);
            float2 e3 = __bfloat1622float2(*(__nv_bfloat162*)&u.w);
            s += v0.x * tanh_fast(e0.x + q0.x);
            s += v0.y * tanh_fast(e0.y + q0.y);
            s += v0.z * tanh_fast(e1.x + q0.z);
            s += v0.w * tanh_fast(e1.y + q0.w);
            s += v1.x * tanh_fast(e2.x + q1.x);
            s += v1.y * tanh_fast(e2.y + q1.y);
            s += v1.z * tanh_fast(e3.x + q1.z);
            s += v1.w * tanh_fast(e3.y + q1.w);
        }
#pragma unroll
        for (int o = 16; o > 0; o >>= 1) s += __shfl_xor_sync(0xffffffffu, s, o);
        if (lane == 0) sc[l] = s;
    }
    __syncthreads();

    if (w == 0) {
        float sv[4];
        float m = -1e30f;
#pragma unroll
        for (int k = 0; k < 4; k++) { sv[k] = sc[lane * 4 + k]; m = fmaxf(m, sv[k]); }
#pragma unroll
        for (int o = 16; o > 0; o >>= 1) m = fmaxf(m, __shfl_xor_sync(0xffffffffu, m, o));
        float e[4], sum = 0.f;
#pragma unroll
        for (int k = 0; k < 4; k++) { e[k] = __expf(sv[k] - m); sum += e[k]; }
#pragma unroll
        for (int o = 16; o > 0; o >>= 1) sum += __shfl_xor_sync(0xffffffffu, sum, o);
        const float ls  = __logf(sum);
        const float inv = 1.0f / sum;
        float* orow = out + ((size_t)b * L + t) * L;
#pragma unroll
        for (int k = 0; k < 4; k++) {
            orow[lane * 4 + k] = sv[k] - m - ls;
            aj[lane * 4 + k]   = e[k] * inv;
        }
    }
    __syncthreads();

    const int h2 = tid * 2;
    float ax = 0.f, ay = 0.f;
    const __nv_bfloat162* base =
        (const __nv_bfloat162*)(g_enc_outh + (size_t)b * L * H + h2);
#pragma unroll 4
    for (int l = 0; l < L; l++) {
        const float a = aj[l];
        float2 v = __bfloat1622float2(base[(size_t)l * (H / 2)]);
        ax += a * v.x;
        ay += a * v.y;
    }
    g_ctx[b * H + h2]     = ax;
    g_ctx[b * H + h2 + 1] = ay;
}

}  // namespace

extern "C" void kernel_launch(void* const* d_in, const int* in_sizes, int n_in,
                              void* d_out, int out_size) {
    (void)in_sizes; (void)n_in; (void)out_size;
    const int*   xs      = (const int*)d_in[0];
    const int*   argsort = (const int*)d_in[2];
    const float* enc_Wi  = (const float*)d_in[3];
    const float* enc_Wh  = (const float*)d_in[4];
    const float* enc_b   = (const float*)d_in[5];
    const float* dec_Wi  = (const float*)d_in[6];
    const float* dec_Wh  = (const float*)d_in[7];
    const float* dec_b   = (const float*)d_in[8];
    const float* w1      = (const float*)d_in[9];
    const float* w2      = (const float*)d_in[10];
    const float* vt      = (const float*)d_in[11];
    float* out = (float*)d_out;

    float *p_h, *p_ctx, *p_encout, *p_ewh4, *p_eb4, *p_ewi4, *p_dw4, *p_db4, *p_dwi4;
    float *p_zpart, *p_qpartb;
    cudaGetSymbolAddress((void**)&p_h,      g_h);
    cudaGetSymbolAddress((void**)&p_ctx,    g_ctx);
    cudaGetSymbolAddress((void**)&p_encout, g_enc_out);
    cudaGetSymbolAddress((void**)&p_ewh4,   g_ewh4);
    cudaGetSymbolAddress((void**)&p_eb4,    g_eb4);
    cudaGetSymbolAddress((void**)&p_ewi4,   g_ewi4);
    cudaGetSymbolAddress((void**)&p_dw4,    g_dw4);
    cudaGetSymbolAddress((void**)&p_db4,    g_db4);
    cudaGetSymbolAddress((void**)&p_dwi4,   g_dwi4);
    cudaGetSymbolAddress((void**)&p_zpart,  g_zpart);
    cudaGetSymbolAddress((void**)&p_qpartb, g_qpartb);

    k_init<<<128, 256>>>();
    k_repack_enc<<<256, 256>>>(enc_Wh, enc_b, enc_Wi);
    k_repack_dec<<<512, 256>>>(dec_Wi, dec_Wh, dec_b);

    const dim3 enc_grid(H4 / 128, B / 128, 4);      // (16, 2, 4) = 128 CTAs
    const dim3 dec_grid(H4 / 128, B / 128, 8);      // (16, 2, 8) = 256 CTAs
    const dim3 q_grid(H / 128, B / 128, 8);         // (4, 2, 8)  = 64 CTAs
    const dim3 w1_grid(H / 128, (B * L) / 128, 1);  // (4, 256)   = 1024 CTAs

    // ---- encoder: 128 fused LSTM steps (GEMM + inline split-K fixup/gates) ----
    for (int t = 0; t < L; t++) {
        const float* hp = p_h + (size_t)(t & 1) * (B * H);
        k_gemm<512, 4, H4, 0><<<enc_grid, 256>>>(
            p_ewh4, hp, nullptr, p_zpart, p_eb4, p_ewi4, xs, nullptr, t);
    }

    // ---- hoisted projection enc_w1 = enc_out @ w1^T (bf16 out, KS=1) ----
    k_gemm<512, 1, H, 3><<<w1_grid, 256>>>(
        w1, p_encout, nullptr, nullptr, nullptr, nullptr, nullptr, nullptr, 0);

    // ---- decoder: 128 steps of q-proj -> attention -> fused LSTM ----
    for (int t = 0; t < L; t++) {
        const float* hp = p_h + (size_t)(t & 1) * (B * H);
        k_gemm<512, 8, H, 2><<<q_grid, 256>>>(
            w2, hp, nullptr, p_qpartb, nullptr, nullptr, nullptr, nullptr, t);
        k_attn<<<B, 256>>>(vt, out, t);
        k_gemm<1024, 8, H4, 1><<<dec_grid, 256>>>(
            p_dw4, p_ctx, hp, p_zpart, p_db4, p_dwi4, xs, argsort, t);
    }
}

// round 8
// speedup vs baseline: 1.4465x; 1.4465x over previous
#include <cuda_runtime.h>
#include <cuda_bf16.h>
#include <math.h>

namespace {

constexpr int B  = 256;
constexpr int L  = 128;
constexpr int H  = 512;
constexpr int H4 = 2048;

// ---------------- device state (allocation-free scratch) ----------------
__device__ float g_h[2][B * H];                          // hidden, double buffered by parity
__device__ float g_c[B * H];                             // cell
__device__ float g_enc_out[(size_t)B * L * H];           // fp32 [b*L+l][h] (encw1 A input)
__device__ __nv_bfloat16 g_enc_outh[(size_t)B * L * H];  // bf16 [b][l][h] (attn context)
__device__ __nv_bfloat16 g_enc_w1h[(size_t)B * L * H];   // bf16 [b*L+l][h] (attn scores)
__device__ float g_ctx[B * H];                           // attention context
__device__ float g_dec_in[2][B];                         // decoder scalar input
__device__ float g_ew4[H4 * H];                          // enc_Wh, gate-interleaved rows n'=4h+g
__device__ float g_eb4[H4];                              // enc bias, interleaved
__device__ float g_ewi4[H4];                             // enc Wi (scalar input), interleaved
__device__ float g_dw4[H4 * 1024];                       // dec [Wi(ctx)|Wh], interleaved, stride 1024
__device__ float g_db4[H4];
__device__ float g_dwi4[H4];                             // dec Wi last column, interleaved
__device__ float g_zpart[2 * B * H4];                    // split-K partials, [kz][b][n'=4h+g]
__device__ float g_qpart[8 * B * H];                     // split-K partials for q

// ---------------- math helpers ----------------
__device__ __forceinline__ float sigmoid_acc(float x) {
    return 1.0f / (1.0f + __expf(-x));
}
__device__ __forceinline__ float tanh_acc(float x) {
    float e = __expf(-2.0f * fabsf(x));
    float r = (1.0f - e) / (1.0f + e);
    return copysignf(r, x);
}
__device__ __forceinline__ float tanh_fast(float x) {
    float y;
    asm("tanh.approx.f32 %0, %1;" : "=f"(y) : "f"(x));
    return y;
}

// ---------------- init ----------------
__global__ void k_init() {
    int i = blockIdx.x * blockDim.x + threadIdx.x;
    int stride = gridDim.x * blockDim.x;
    for (int j = i; j < B * H; j += stride) {
        g_h[0][j] = 0.0f;
        g_c[j]    = 0.0f;
    }
    if (i < B) g_dec_in[0][i] = 0.0f;
}

// ---------------- one-time repacks: gate-interleave rows (n' = 4h + g) ----------------
__global__ void k_repack_enc(const float* __restrict__ ewh,
                             const float* __restrict__ eb,
                             const float* __restrict__ ewi) {
    int i = blockIdx.x * blockDim.x + threadIdx.x;
    int stride = gridDim.x * blockDim.x;
    for (int j = i; j < H4 * H; j += stride) {
        int np = j >> 9;
        int k  = j & (H - 1);
        int hh = np >> 2, g = np & 3;
        g_ew4[j] = ewh[(g * H + hh) * H + k];
    }
    if (i < H4) {
        int hh = i >> 2, g = i & 3;
        g_eb4[i]  = eb[g * H + hh];
        g_ewi4[i] = ewi[g * H + hh];
    }
}

__global__ void k_repack_dec(const float* __restrict__ dwi,
                             const float* __restrict__ dwh,
                             const float* __restrict__ db) {
    int i = blockIdx.x * blockDim.x + threadIdx.x;
    int stride = gridDim.x * blockDim.x;
    for (int j = i; j < H4 * 1024; j += stride) {
        int np = j >> 10;
        int k  = j & 1023;
        int hh = np >> 2, g = np & 3;
        int row = g * H + hh;
        g_dw4[j] = (k < H) ? dwi[row * (H + 1) + k] : dwh[row * H + (k - H)];
    }
    if (i < H4) {
        int hh = i >> 2, g = i & 3;
        g_db4[i]  = db[g * H + hh];
        g_dwi4[i] = dwi[(g * H + hh) * (H + 1) + H];
    }
}

// ---------------- generic split-K GEMM (R2, proven):  part[kz] = A @ W^T over K-chunk ----
// C is [256 x N], A rows have stride 512 (CONCAT: k<512 from A0=ctx, else A1=h).
// Tile 64x64, micro 4x4, BK=16, double-buffered smem, one sync per tile.
// grid = (N/64, 4, KS), 256 threads.
template <int KTOT, int KS, bool CONCAT>
__global__ void __launch_bounds__(256) k_gemm(
    const float* __restrict__ W,    // [N x KTOT]
    const float* __restrict__ A0,
    const float* __restrict__ A1,
    float* __restrict__ part)       // [KS][256][N]
{
    constexpr int KC = KTOT / KS;
    constexpr int NT = KC / 16;

    __shared__ float As[2][16][68];
    __shared__ float Bs[2][16][68];

    const int tid = threadIdx.x;
    const int tx  = tid & 15;           // n quad
    const int ty  = tid >> 4;           // m quad
    const int n0  = blockIdx.x * 64;
    const int m0  = blockIdx.y * 64;
    const int kbase = blockIdx.z * KC;
    const int N   = gridDim.x * 64;

    const int rl = tid >> 2;            // 0..63 (load row within tile)
    const int kl = (tid & 3) * 4;       // 0,4,8,12 (load k quad)

    float acc[4][4] = {};

    auto gload = [&](int k0, float4& av, float4& wv) {
        const int k = k0 + kl;
        const float* asrc;
        if (CONCAT) {
            asrc = (k < 512) ? (A0 + (m0 + rl) * 512 + k)
                             : (A1 + (m0 + rl) * 512 + (k - 512));
        } else {
            asrc = A0 + (m0 + rl) * 512 + k;
        }
        av = *(const float4*)asrc;
        wv = *(const float4*)&W[(size_t)(n0 + rl) * KTOT + k];
    };
    auto sstore = [&](int buf, float4 av, float4 wv) {
        As[buf][kl + 0][rl] = av.x; As[buf][kl + 1][rl] = av.y;
        As[buf][kl + 2][rl] = av.z; As[buf][kl + 3][rl] = av.w;
        Bs[buf][kl + 0][rl] = wv.x; Bs[buf][kl + 1][rl] = wv.y;
        Bs[buf][kl + 2][rl] = wv.z; Bs[buf][kl + 3][rl] = wv.w;
    };

    {
        float4 av, wv;
        gload(kbase, av, wv);
        sstore(0, av, wv);
    }
    __syncthreads();

    for (int t = 0; t < NT; t++) {
        float4 av, wv;
        const bool more = (t + 1 < NT);
        if (more) gload(kbase + (t + 1) * 16, av, wv);

        const int cb = t & 1;
#pragma unroll
        for (int k = 0; k < 16; k++) {
            float4 a = *(const float4*)&As[cb][k][ty * 4];
            float4 b = *(const float4*)&Bs[cb][k][tx * 4];
            acc[0][0] += a.x * b.x; acc[0][1] += a.x * b.y; acc[0][2] += a.x * b.z; acc[0][3] += a.x * b.w;
            acc[1][0] += a.y * b.x; acc[1][1] += a.y * b.y; acc[1][2] += a.y * b.z; acc[1][3] += a.y * b.w;
            acc[2][0] += a.z * b.x; acc[2][1] += a.z * b.y; acc[2][2] += a.z * b.z; acc[2][3] += a.z * b.w;
            acc[3][0] += a.w * b.x; acc[3][1] += a.w * b.y; acc[3][2] += a.w * b.z; acc[3][3] += a.w * b.w;
        }
        if (more) sstore(cb ^ 1, av, wv);  // writes the buffer NOT being read: no race
        __syncthreads();
    }

    float* dst = part + (size_t)blockIdx.z * 256 * N;
#pragma unroll
    for (int i = 0; i < 4; i++) {
        float4 o = make_float4(acc[i][0], acc[i][1], acc[i][2], acc[i][3]);
        *(float4*)&dst[(size_t)(m0 + ty * 4 + i) * N + n0 + tx * 4] = o;
    }
}

// ---------------- gates: coalesced float4 partial reduce + activations + state update ------
// Gate-interleaved partials: zpart[kz][b][4h+g]. One thread per (b,h); threads within a
// warp read consecutive 16B quads -> fully coalesced. grid = B*H/256 = 512, 256 threads.
template <bool DEC>
__global__ void __launch_bounds__(256) k_gates(
    const float* __restrict__ bias4,   // [2048] interleaved
    const float* __restrict__ wiv4,    // [2048] interleaved scalar-input weights
    const int*   __restrict__ xs,
    const int*   __restrict__ argsort,
    int t)
{
    const int idx = blockIdx.x * 256 + threadIdx.x;
    const int b = idx >> 9;
    const int h = idx & (H - 1);
    const int np = h << 2;
    const int p = t & 1;

    const float xb = DEC ? g_dec_in[p][b] : (float)xs[b * L + t];

    float4 z0 = *(const float4*)&g_zpart[(size_t)b * H4 + np];
    float4 z1 = *(const float4*)&g_zpart[(size_t)(B * H4) + (size_t)b * H4 + np];
    const float4 bb = *(const float4*)&bias4[np];
    const float4 ww = *(const float4*)&wiv4[np];

    const float zi = z0.x + z1.x + bb.x + xb * ww.x;
    const float zf = z0.y + z1.y + bb.y + xb * ww.y;
    const float zg = z0.z + z1.z + bb.z + xb * ww.z;
    const float zo = z0.w + z1.w + bb.w + xb * ww.w;

    const float c  = sigmoid_acc(zf) * g_c[idx] + sigmoid_acc(zi) * tanh_acc(zg);
    const float hn = sigmoid_acc(zo) * tanh_acc(c);
    g_c[idx] = c;
    g_h[p ^ 1][idx] = hn;
    if (!DEC) {
        const size_t eo = ((size_t)b * L + t) * H + h;
        g_enc_out[eo]  = hn;
        g_enc_outh[eo] = __float2bfloat16_rn(hn);
    }
    if (DEC && h == 0) {
        g_dec_in[p ^ 1][b] = (float)xs[b * L + argsort[b * L + t]];
    }
}

// ---------------- enc_w1 = enc_out @ w1^T -> bf16  (M=32768, N=512, K=512) ----------------
// (R3 version, proven) grid = (8, 512), 256 threads.
__global__ void __launch_bounds__(256) k_encw1(const float* __restrict__ w1) {
    __shared__ float As[16][68];
    __shared__ float Bs[16][68];

    const int tid = threadIdx.x;
    const int tx = tid & 15;
    const int ty = tid >> 4;
    const int n0 = blockIdx.x * 64;
    const int m0 = blockIdx.y * 64;

    const int rl = tid >> 2;
    const int kl = (tid & 3) * 4;

    float acc[4][4] = {};

    for (int k0 = 0; k0 < H; k0 += 16) {
        __syncthreads();
        {
            float4 av = *(const float4*)&g_enc_out[(size_t)(m0 + rl) * H + k0 + kl];
            As[kl + 0][rl] = av.x; As[kl + 1][rl] = av.y;
            As[kl + 2][rl] = av.z; As[kl + 3][rl] = av.w;
            float4 bv = *(const float4*)&w1[(n0 + rl) * H + k0 + kl];
            Bs[kl + 0][rl] = bv.x; Bs[kl + 1][rl] = bv.y;
            Bs[kl + 2][rl] = bv.z; Bs[kl + 3][rl] = bv.w;
        }
        __syncthreads();
#pragma unroll
        for (int k = 0; k < 16; k++) {
            float4 a = *(const float4*)&As[k][ty * 4];
            float4 w = *(const float4*)&Bs[k][tx * 4];
            acc[0][0] += a.x * w.x; acc[0][1] += a.x * w.y; acc[0][2] += a.x * w.z; acc[0][3] += a.x * w.w;
            acc[1][0] += a.y * w.x; acc[1][1] += a.y * w.y; acc[1][2] += a.y * w.z; acc[1][3] += a.y * w.w;
            acc[2][0] += a.z * w.x; acc[2][1] += a.z * w.y; acc[2][2] += a.z * w.z; acc[2][3] += a.z * w.w;
            acc[3][0] += a.w * w.x; acc[3][1] += a.w * w.y; acc[3][2] += a.w * w.z; acc[3][3] += a.w * w.w;
        }
    }
#pragma unroll
    for (int i = 0; i < 4; i++) {
        __nv_bfloat162 p0 = __floats2bfloat162_rn(acc[i][0], acc[i][1]);
        __nv_bfloat162 p1 = __floats2bfloat162_rn(acc[i][2], acc[i][3]);
        uint2 pk = make_uint2(*(unsigned*)&p0, *(unsigned*)&p1);
        *(uint2*)&g_enc_w1h[(size_t)(m0 + ty * 4 + i) * H + n0 + tx * 4] = pk;
    }
}

// ---------------- attention: q-reduce + scores + softmax/log_softmax + context ------------
// (R3 version, proven) One block per batch element; big reads are bf16.
__global__ void __launch_bounds__(256) k_attn(const float* __restrict__ vt,
                                              float* __restrict__ out, int t) {
    __shared__ float q_s[H];
    __shared__ float vt_s[H];
    __shared__ float sc[L];
    __shared__ float aj[L];

    const int b = blockIdx.x;
    const int tid = threadIdx.x;
    const int lane = tid & 31;
    const int w = tid >> 5;

    for (int i = tid; i < H; i += 256) {
        float s = 0.0f;
#pragma unroll
        for (int sp = 0; sp < 8; sp++)
            s += g_qpart[(size_t)sp * (B * H) + b * H + i];
        q_s[i]  = s;
        vt_s[i] = vt[i];
    }
    __syncthreads();

#pragma unroll 1
    for (int li = 0; li < 16; li++) {
        const int l = w * 16 + li;
        const uint4* e8 = (const uint4*)(g_enc_w1h + (size_t)(b * L + l) * H);
        float s = 0.f;
#pragma unroll
        for (int j = 0; j < 2; j++) {
            const int base = (lane + j * 32) * 8;
            uint4 u = e8[lane + j * 32];
            float4 q0 = *(const float4*)&q_s[base];
            float4 q1 = *(const float4*)&q_s[base + 4];
            float4 v0 = *(const float4*)&vt_s[base];
            float4 v1 = *(const float4*)&vt_s[base + 4];
            float2 e0 = __bfloat1622float2(*(__nv_bfloat162*)&u.x);
            float2 e1 = __bfloat1622float2(*(__nv_bfloat162*)&u.y);
            float2 e2 = __bfloat1622float2(*(__nv_bfloat162*)&u.z);
            float2 e3 = __bfloat1622float2(*(__nv_bfloat162*)&u.w);
            s += v0.x * tanh_fast(e0.x + q0.x);
            s += v0.y * tanh_fast(e0.y + q0.y);
            s += v0.z * tanh_fast(e1.x + q0.z);
            s += v0.w * tanh_fast(e1.y + q0.w);
            s += v1.x * tanh_fast(e2.x + q1.x);
            s += v1.y * tanh_fast(e2.y + q1.y);
            s += v1.z * tanh_fast(e3.x + q1.z);
            s += v1.w * tanh_fast(e3.y + q1.w);
        }
#pragma unroll
        for (int o = 16; o > 0; o >>= 1) s += __shfl_xor_sync(0xffffffffu, s, o);
        if (lane == 0) sc[l] = s;
    }
    __syncthreads();

    if (w == 0) {
        float sv[4];
        float m = -1e30f;
#pragma unroll
        for (int k = 0; k < 4; k++) { sv[k] = sc[lane * 4 + k]; m = fmaxf(m, sv[k]); }
#pragma unroll
        for (int o = 16; o > 0; o >>= 1) m = fmaxf(m, __shfl_xor_sync(0xffffffffu, m, o));
        float e[4], sum = 0.f;
#pragma unroll
        for (int k = 0; k < 4; k++) { e[k] = __expf(sv[k] - m); sum += e[k]; }
#pragma unroll
        for (int o = 16; o > 0; o >>= 1) sum += __shfl_xor_sync(0xffffffffu, sum, o);
        const float ls  = __logf(sum);
        const float inv = 1.0f / sum;
        float* orow = out + ((size_t)b * L + t) * L;
#pragma unroll
        for (int k = 0; k < 4; k++) {
            orow[lane * 4 + k] = sv[k] - m - ls;
            aj[lane * 4 + k]   = e[k] * inv;
        }
    }
    __syncthreads();

    const int h2 = tid * 2;
    float ax = 0.f, ay = 0.f;
    const __nv_bfloat162* base =
        (const __nv_bfloat162*)(g_enc_outh + (size_t)b * L * H + h2);
#pragma unroll 4
    for (int l = 0; l < L; l++) {
        const float a = aj[l];
        float2 v = __bfloat1622float2(base[(size_t)l * (H / 2)]);
        ax += a * v.x;
        ay += a * v.y;
    }
    g_ctx[b * H + h2]     = ax;
    g_ctx[b * H + h2 + 1] = ay;
}

}  // namespace

extern "C" void kernel_launch(void* const* d_in, const int* in_sizes, int n_in,
                              void* d_out, int out_size) {
    (void)in_sizes; (void)n_in; (void)out_size;
    const int*   xs      = (const int*)d_in[0];
    const int*   argsort = (const int*)d_in[2];
    const float* enc_Wi  = (const float*)d_in[3];
    const float* enc_Wh  = (const float*)d_in[4];
    const float* enc_b   = (const float*)d_in[5];
    const float* dec_Wi  = (const float*)d_in[6];
    const float* dec_Wh  = (const float*)d_in[7];
    const float* dec_b   = (const float*)d_in[8];
    const float* w1      = (const float*)d_in[9];
    const float* w2      = (const float*)d_in[10];
    const float* vt      = (const float*)d_in[11];
    float* out = (float*)d_out;

    float *p_h, *p_ctx, *p_ew4, *p_eb4, *p_ewi4, *p_dw4, *p_db4, *p_dwi4, *p_zpart, *p_qpart;
    cudaGetSymbolAddress((void**)&p_h,     g_h);
    cudaGetSymbolAddress((void**)&p_ctx,   g_ctx);
    cudaGetSymbolAddress((void**)&p_ew4,   g_ew4);
    cudaGetSymbolAddress((void**)&p_eb4,   g_eb4);
    cudaGetSymbolAddress((void**)&p_ewi4,  g_ewi4);
    cudaGetSymbolAddress((void**)&p_dw4,   g_dw4);
    cudaGetSymbolAddress((void**)&p_db4,   g_db4);
    cudaGetSymbolAddress((void**)&p_dwi4,  g_dwi4);
    cudaGetSymbolAddress((void**)&p_zpart, g_zpart);
    cudaGetSymbolAddress((void**)&p_qpart, g_qpart);

    k_init<<<128, 256>>>();
    k_repack_enc<<<256, 256>>>(enc_Wh, enc_b, enc_Wi);
    k_repack_dec<<<512, 256>>>(dec_Wi, dec_Wh, dec_b);

    const dim3 gates_grid(B * H / 256);             // 512
    const dim3 lstm_gemm(H4 / 64, B / 64, 2);       // (32, 4, 2) = 256 CTAs
    const dim3 q_gemm(H / 64, B / 64, 8);           // (8, 4, 8)  = 256 CTAs
    const dim3 encw1_grid(H / 64, (B * L) / 64);    // (8, 512)

    // ---- encoder: 128 steps of split-K GEMM + gates ----
    for (int t = 0; t < L; t++) {
        const float* hp = p_h + (size_t)(t & 1) * (B * H);
        k_gemm<512, 2, false><<<lstm_gemm, 256>>>(p_ew4, hp, nullptr, p_zpart);
        k_gates<false><<<gates_grid, 256>>>(p_eb4, p_ewi4, xs, nullptr, t);
    }

    // ---- hoisted projection enc_w1 = enc_out @ w1^T (bf16 out) ----
    k_encw1<<<encw1_grid, 256>>>(w1);

    // ---- decoder: 128 steps of q-proj -> attention -> GEMM + gates ----
    for (int t = 0; t < L; t++) {
        const float* hp = p_h + (size_t)(t & 1) * (B * H);
        k_gemm<512, 8, false><<<q_gemm, 256>>>(w2, hp, nullptr, p_qpart);
        k_attn<<<B, 256>>>(vt, out, t);
        k_gemm<1024, 2, true><<<lstm_gemm, 256>>>(p_dw4, p_ctx, hp, p_zpart);
        k_gates<true><<<gates_grid, 256>>>(p_db4, p_dwi4, xs, argsort, t);
    }
}